// round 15
// baseline (speedup 1.0000x reference)
#include <cuda_runtime.h>
#include <cuda_fp16.h>
#include <cstdint>

#define TOK    8192
#define HID    3072
#define INTERC 8192
#define TILEB  16384u         // one 128x64 f16 tile, swizzled, bytes
// 128-wide K chunks (two 64-tiles each)
#define NK1    (HID / 128)    // 24
#define NK2    (INTERC / 128) // 64
#define NK1T   (HID / 64)     // 48 tiles per rowblock (gmem layout)
#define NK2T   (INTERC / 64)  // 128

#define NSTG1  2
#define NSTG2  3

#define STG1   98304u         // Ag 32K | Au 32K | B 32K
#define SMEM1  (1024u + NSTG1 * STG1)   // 197632
#define STG2   65536u         // A 32K | B 32K
#define SMEM2  (1024u + NSTG2 * STG2)   // 197632

// cg2 kind::f16: dtype=F32, a/b=F16, N=256, M=256
#define IDESC2 ((1u << 4) | (32u << 17) | (16u << 24))

#if !defined(__CUDA_ARCH__) || defined(__CUDA_ARCH_FEAT_SM103_ALL) || defined(__CUDA_ARCH_FEAT_SM100_ALL) || defined(__CUDA_ARCH_FEAT_SM101_ALL)
#define HAS_TCGEN05 1
#else
#define HAS_TCGEN05 0
#endif

// tiled+swizzled scratch: [rowblock][ktile64][16KB tile]
__device__ __align__(1024) __half g_xh [(size_t)TOK * HID];
__device__ __align__(1024) __half g_w1h[(size_t)(2 * INTERC) * HID];
__device__ __align__(1024) __half g_w2h[(size_t)HID * INTERC];
__device__ __align__(1024) __half g_hid[(size_t)TOK * INTERC];

__device__ __forceinline__ uint32_t smem_u32(const void* p) {
    uint32_t a;
    asm("{ .reg .u64 t; cvta.to.shared.u64 t, %1; cvt.u32.u64 %0, t; }" : "=r"(a) : "l"(p));
    return a;
}
#define SWZ(o) ((o) ^ (((o) >> 3) & 0x70))

#define LFULL(sb, s)  ((sb) + 32u + 32u * (uint32_t)(s))
#define EMPTYB(sb, s) ((sb) + 40u + 32u * (uint32_t)(s))
#define GFULL(sb, s)  ((sb) + 48u + 32u * (uint32_t)(s))

__device__ __forceinline__ uint64_t make_desc(uint32_t addr) {
    const uint64_t base = (uint64_t(2) << 61) | (uint64_t(1) << 46) |
                          (uint64_t(64) << 32) | (uint64_t(1) << 16);
    return base | ((uint64_t)(addr >> 4) & 0x3FFF);
}
__device__ __forceinline__ void cpa16(uint32_t dst, const void* src) {
    asm volatile("cp.async.cg.shared.global [%0], [%1], 16;" :: "r"(dst), "l"(src));
}
__device__ __forceinline__ void cpa_arrive(uint32_t mbar) {
    asm volatile("cp.async.mbarrier.arrive.noinc.shared.b64 [%0];" :: "r"(mbar) : "memory");
}
// pre-swizzled contiguous 32KB (two adjacent tiles): 256 threads x 8 x 16B
__device__ __forceinline__ void copy_tile32(uint32_t sdst, const char* src, int tid) {
#pragma unroll
    for (int i = 0; i < 8; i++) {
        uint32_t off = (uint32_t)(tid * 16 + i * 4096);
        cpa16(sdst + off, src + off);
    }
}

#if HAS_TCGEN05
__device__ __forceinline__ void mma2_f16_ss(uint32_t d, uint64_t a, uint64_t b, uint32_t en) {
    asm volatile("{\n\t.reg .pred p;\n\tsetp.ne.u32 p, %4, 0;\n\t"
        "tcgen05.mma.cta_group::2.kind::f16 [%0], %1, %2, %3, {%5, %5, %5, %5, %5, %5, %5, %5}, p;\n\t}"
        :: "r"(d), "l"(a), "l"(b), "r"(IDESC2), "r"(en), "r"(0u) : "memory");
}
#define TCG_ALLOC2(sa, n)  asm volatile("tcgen05.alloc.cta_group::2.sync.aligned.shared::cta.b32 [%0], %1;" :: "r"(sa), "r"((uint32_t)(n)) : "memory")
#define TCG_DEALLOC2(t, n) asm volatile("tcgen05.dealloc.cta_group::2.sync.aligned.b32 %0, %1;" :: "r"(t), "r"((uint32_t)(n)))
#define TCG_RELQ2()        asm volatile("tcgen05.relinquish_alloc_permit.cta_group::2.sync.aligned;")
#define TCG_COMMIT_MC(a)   asm volatile("tcgen05.commit.cta_group::2.mbarrier::arrive::one.shared::cluster.multicast::cluster.b64 [%0], %1;" :: "r"(a), "h"((uint16_t)3) : "memory")
#define TCG_FENCE_AFTER()  asm volatile("tcgen05.fence::after_thread_sync;" ::: "memory")
#define TCG_WAIT_LD()      asm volatile("tcgen05.wait::ld.sync.aligned;" ::: "memory")

#define LDTM_X32(r, a)                                                            \
    asm volatile("tcgen05.ld.sync.aligned.32x32b.x32.b32 "                        \
        "{%0, %1, %2, %3, %4, %5, %6, %7, %8, %9, %10, %11, %12, %13, %14, %15, " \
        " %16, %17, %18, %19, %20, %21, %22, %23, %24, %25, %26, %27, %28, %29, %30, %31}, [%32];" \
        : "=r"((r)[0]),  "=r"((r)[1]),  "=r"((r)[2]),  "=r"((r)[3]),              \
          "=r"((r)[4]),  "=r"((r)[5]),  "=r"((r)[6]),  "=r"((r)[7]),              \
          "=r"((r)[8]),  "=r"((r)[9]),  "=r"((r)[10]), "=r"((r)[11]),             \
          "=r"((r)[12]), "=r"((r)[13]), "=r"((r)[14]), "=r"((r)[15]),             \
          "=r"((r)[16]), "=r"((r)[17]), "=r"((r)[18]), "=r"((r)[19]),             \
          "=r"((r)[20]), "=r"((r)[21]), "=r"((r)[22]), "=r"((r)[23]),             \
          "=r"((r)[24]), "=r"((r)[25]), "=r"((r)[26]), "=r"((r)[27]),             \
          "=r"((r)[28]), "=r"((r)[29]), "=r"((r)[30]), "=r"((r)[31])              \
        : "r"(a))
#endif

#define MBAR_INIT(a, c)   asm volatile("mbarrier.init.shared.b64 [%0], %1;" :: "r"(a), "r"((uint32_t)(c)) : "memory")
#define MBAR_WAIT(addr, ph) do {                                                 \
    uint32_t _d;                                                                 \
    asm volatile("{\n\t.reg .pred p;\n\t"                                        \
        "mbarrier.try_wait.parity.acquire.cta.shared::cta.b64 p, [%1], %2;\n\t"  \
        "selp.b32 %0, 1, 0, p;\n\t}" : "=r"(_d) : "r"(addr), "r"(ph) : "memory");\
    while (!_d)                                                                  \
        asm volatile("{\n\t.reg .pred p;\n\t"                                    \
            "mbarrier.try_wait.parity.acquire.cta.shared::cta.b64 p, [%1], %2, 0x989680;\n\t" \
            "selp.b32 %0, 1, 0, p;\n\t}" : "=r"(_d) : "r"(addr), "r"(ph) : "memory"); \
} while (0)
#define MBAR_WAIT_CL(addr, ph) do {                                              \
    uint32_t _d;                                                                 \
    asm volatile("{\n\t.reg .pred p;\n\t"                                        \
        "mbarrier.try_wait.parity.acquire.cluster.shared::cta.b64 p, [%1], %2;\n\t" \
        "selp.b32 %0, 1, 0, p;\n\t}" : "=r"(_d) : "r"(addr), "r"(ph) : "memory");\
    while (!_d)                                                                  \
        asm volatile("{\n\t.reg .pred p;\n\t"                                    \
            "mbarrier.try_wait.parity.acquire.cluster.shared::cta.b64 p, [%1], %2, 0x989680;\n\t" \
            "selp.b32 %0, 1, 0, p;\n\t}" : "=r"(_d) : "r"(addr), "r"(ph) : "memory"); \
} while (0)
#define ARRIVE_LEADER(addr)                                                      \
    asm volatile("{\n\t.reg .b32 ra;\n\t"                                        \
        "mapa.shared::cluster.u32 ra, %0, 0;\n\t"                                \
        "mbarrier.arrive.shared::cluster.b64 _, [ra];\n\t}"                      \
        :: "r"(addr) : "memory")
#define CLUSTER_SYNC() do {                                                      \
    asm volatile("barrier.cluster.arrive.aligned;" ::: "memory");                \
    asm volatile("barrier.cluster.wait.aligned;" ::: "memory");                  \
} while (0)

// ---- converts: row-major -> tiled [row/128][col/64][16KB SW128-swizzled] ------
__global__ void __launch_bounds__(256) cvt_i32_t(const int* __restrict__ s,
                                                 __half* __restrict__ d,
                                                 int cols, unsigned ngrp) {
    unsigned i = blockIdx.x * 256u + threadIdx.x;
    if (i >= ngrp) return;
    unsigned e = i * 8u;
    unsigned row = e / (unsigned)cols, col = e % (unsigned)cols;
    const int4* p = (const int4*)(s + (size_t)row * cols + col);
    int4 a = p[0], b = p[1];
    __half2 h0 = __floats2half2_rn((float)a.x, (float)a.y);
    __half2 h1 = __floats2half2_rn((float)a.z, (float)a.w);
    __half2 h2 = __floats2half2_rn((float)b.x, (float)b.y);
    __half2 h3 = __floats2half2_rn((float)b.z, (float)b.w);
    uint4 v = make_uint4(*(uint32_t*)&h0, *(uint32_t*)&h1, *(uint32_t*)&h2, *(uint32_t*)&h3);
    unsigned nkc = (unsigned)cols >> 6;
    size_t tile = (size_t)(row >> 7) * nkc + (col >> 6);
    uint32_t off = (row & 127u) * 128u + (col & 63u) * 2u;
    *(uint4*)((char*)d + tile * TILEB + SWZ(off)) = v;
}
__global__ void __launch_bounds__(256) cvt_f32_t(const float* __restrict__ s,
                                                 __half* __restrict__ d,
                                                 int cols, unsigned ngrp) {
    unsigned i = blockIdx.x * 256u + threadIdx.x;
    if (i >= ngrp) return;
    unsigned e = i * 8u;
    unsigned row = e / (unsigned)cols, col = e % (unsigned)cols;
    const float4* p = (const float4*)(s + (size_t)row * cols + col);
    float4 a = p[0], b = p[1];
    __half2 h0 = __floats2half2_rn(a.x, a.y);
    __half2 h1 = __floats2half2_rn(a.z, a.w);
    __half2 h2 = __floats2half2_rn(b.x, b.y);
    __half2 h3 = __floats2half2_rn(b.z, b.w);
    uint4 v = make_uint4(*(uint32_t*)&h0, *(uint32_t*)&h1, *(uint32_t*)&h2, *(uint32_t*)&h3);
    unsigned nkc = (unsigned)cols >> 6;
    size_t tile = (size_t)(row >> 7) * nkc + (col >> 6);
    uint32_t off = (row & 127u) * 128u + (col & 63u) * 2u;
    *(uint4*)((char*)d + tile * TILEB + SWZ(off)) = v;
}

// ---------------- GEMM1 (cg2, 128-wide K chunks) --------------------------------
__global__ void __launch_bounds__(320, 1) __cluster_dims__(2, 1, 1)
ffn_gemm1(const float* __restrict__ gus) {
#if HAS_TCGEN05
    extern __shared__ char smem[];
    uint32_t sb = smem_u32(smem);
    const int tid = threadIdx.x, wid = tid >> 5, lid = tid & 31;
    uint32_t rank;
    asm("mov.u32 %0, %%cluster_ctarank;" : "=r"(rank));
    const int by = blockIdx.y, bz = blockIdx.z;
    const int t0 = by * 256, g0 = bz * 256;

    if (wid == 0) TCG_ALLOC2(sb, 512);
    if (tid == 0) {
#pragma unroll
        for (int s = 0; s < NSTG1; s++) {
            MBAR_INIT(LFULL(sb, s), 256);
            MBAR_INIT(EMPTYB(sb, s), 1);
            MBAR_INIT(GFULL(sb, s), 2);
        }
    }
    __syncthreads();
    uint32_t tb;
    asm volatile("ld.shared.b32 %0, [%1];" : "=r"(tb) : "r"(sb));
    CLUSTER_SYNC();

    const char* wb = (const char*)g_w1h;
    const char* xb = (const char*)g_xh;
    const size_t rbg = (size_t)(2 * bz + (int)rank);
    const size_t rbu = (size_t)(INTERC / 128 + 2 * bz + (int)rank);
    const size_t rbx = (size_t)(2 * by + (int)rank);

    if (tid < 256) {
        // producers: 3 contiguous 32KB copies per 128-wide chunk
        for (int kc = 0; kc < NK1; kc++) {
            const int s = kc % NSTG1;
            if (kc >= NSTG1)
                MBAR_WAIT(EMPTYB(sb, s), (uint32_t)((kc / NSTG1 + 1) & 1));
            const uint32_t base = sb + 1024u + (uint32_t)s * STG1;
            copy_tile32(base,          wb + (rbg * NK1T + 2 * kc) * TILEB, tid);
            copy_tile32(base + 32768u, wb + (rbu * NK1T + 2 * kc) * TILEB, tid);
            copy_tile32(base + 65536u, xb + (rbx * NK1T + 2 * kc) * TILEB, tid);
            cpa_arrive(LFULL(sb, s));
        }
    } else if (tid == 288) {
        for (int kc = 0; kc < NK1; kc++) {
            const int s = kc % NSTG1, r = kc / NSTG1;
            MBAR_WAIT(LFULL(sb, s), (uint32_t)(r & 1));
            ARRIVE_LEADER(GFULL(sb, s));
        }
    } else if (tid == 256 && rank == 0) {
        for (int kc = 0; kc < NK1; kc++) {
            const int s = kc % NSTG1, r = kc / NSTG1;
            MBAR_WAIT_CL(GFULL(sb, s), (uint32_t)(r & 1));
            asm volatile("fence.proxy.async.shared::cta;" ::: "memory");
            const uint32_t base = sb + 1024u + (uint32_t)s * STG1;
#pragma unroll
            for (int h = 0; h < 2; h++) {
                uint64_t ad = make_desc(base + (uint32_t)h * TILEB);
                uint64_t au = make_desc(base + 32768u + (uint32_t)h * TILEB);
                uint64_t bd = make_desc(base + 65536u + (uint32_t)h * TILEB);
#pragma unroll
                for (int ks = 0; ks < 4; ks++) {
                    uint32_t en = (kc | h | ks) ? 1u : 0u;
                    mma2_f16_ss(tb,        ad + ks * 2, bd + ks * 2, en);
                    mma2_f16_ss(tb + 256u, au + ks * 2, bd + ks * 2, en);
                }
            }
            TCG_COMMIT_MC(EMPTYB(sb, s));
        }
    }

    if (tid < 256) {
        MBAR_WAIT(EMPTYB(sb, (NK1 - 1) % NSTG1), (uint32_t)(((NK1 - 1) / NSTG1) & 1));
        TCG_FENCE_AFTER();
        const int wg = wid >> 2;
        const int o = g0 + (int)rank * 128 + ((wid & 3) << 5) + lid;
        const float sg = gus[o], su = gus[INTERC + o];
        char* hb = (char*)g_hid;
        const size_t tilebase = ((size_t)(2 * by + wg) * NK2T + (size_t)(o >> 6)) * TILEB;
        const uint32_t oc = (uint32_t)(o & 63) * 2u;
#pragma unroll
        for (int cc = 0; cc < 4; cc++) {
            const int cb = wg * 128 + cc * 32;
            uint32_t gr[32], ur[32];
            LDTM_X32(gr, tb + (uint32_t)cb);
            LDTM_X32(ur, tb + 256u + (uint32_t)cb);
            TCG_WAIT_LD();
#pragma unroll
            for (int j = 0; j < 32; j++) {
                float g = __uint_as_float(gr[j]) * sg;
                float u = __uint_as_float(ur[j]) * su;
                float h = g * u * 0.0625f / (1.0f + __expf(-g));
                uint32_t off = (uint32_t)(cc * 32 + j) * 128u + oc;
                *(__half*)(hb + tilebase + SWZ(off)) = __float2half_rn(h);
            }
        }
    }
    __syncthreads();
    CLUSTER_SYNC();
    if (wid == 0) { TCG_RELQ2(); TCG_DEALLOC2(tb, 512); }
    CLUSTER_SYNC();
#endif
}

// ---------------- GEMM2 (cg2, 128-wide K chunks) --------------------------------
__global__ void __launch_bounds__(320, 1) __cluster_dims__(2, 1, 1)
ffn_gemm2(const float* __restrict__ dsc, float* __restrict__ out) {
#if HAS_TCGEN05
    extern __shared__ char smem[];
    uint32_t sb = smem_u32(smem);
    const int tid = threadIdx.x, wid = tid >> 5, lid = tid & 31;
    uint32_t rank;
    asm("mov.u32 %0, %%cluster_ctarank;" : "=r"(rank));
    const int by = blockIdx.y, bz = blockIdx.z;
    const int t0 = by * 256, n0 = bz * 256;

    if (wid == 0) TCG_ALLOC2(sb, 256);
    if (tid == 0) {
#pragma unroll
        for (int s = 0; s < NSTG2; s++) {
            MBAR_INIT(LFULL(sb, s), 256);
            MBAR_INIT(EMPTYB(sb, s), 1);
            MBAR_INIT(GFULL(sb, s), 2);
        }
    }
    __syncthreads();
    uint32_t tb;
    asm volatile("ld.shared.b32 %0, [%1];" : "=r"(tb) : "r"(sb));
    CLUSTER_SYNC();

    const char* wb = (const char*)g_w2h;
    const char* hbs = (const char*)g_hid;
    const size_t rba = (size_t)(2 * bz + (int)rank);
    const size_t rbb = (size_t)(2 * by + (int)rank);

    if (tid < 256) {
        for (int kc = 0; kc < NK2; kc++) {
            const int s = kc % NSTG2;
            if (kc >= NSTG2)
                MBAR_WAIT(EMPTYB(sb, s), (uint32_t)((kc / NSTG2 + 1) & 1));
            const uint32_t base = sb + 1024u + (uint32_t)s * STG2;
            copy_tile32(base,          wb  + (rba * NK2T + 2 * kc) * TILEB, tid);
            copy_tile32(base + 32768u, hbs + (rbb * NK2T + 2 * kc) * TILEB, tid);
            cpa_arrive(LFULL(sb, s));
        }
    } else if (tid == 288) {
        for (int kc = 0; kc < NK2; kc++) {
            const int s = kc % NSTG2, r = kc / NSTG2;
            MBAR_WAIT(LFULL(sb, s), (uint32_t)(r & 1));
            ARRIVE_LEADER(GFULL(sb, s));
        }
    } else if (tid == 256 && rank == 0) {
        for (int kc = 0; kc < NK2; kc++) {
            const int s = kc % NSTG2, r = kc / NSTG2;
            MBAR_WAIT_CL(GFULL(sb, s), (uint32_t)(r & 1));
            asm volatile("fence.proxy.async.shared::cta;" ::: "memory");
            const uint32_t base = sb + 1024u + (uint32_t)s * STG2;
#pragma unroll
            for (int h = 0; h < 2; h++) {
                uint64_t ad = make_desc(base + (uint32_t)h * TILEB);
                uint64_t bd = make_desc(base + 32768u + (uint32_t)h * TILEB);
#pragma unroll
                for (int ks = 0; ks < 4; ks++)
                    mma2_f16_ss(tb, ad + ks * 2, bd + ks * 2, (kc | h | ks) ? 1u : 0u);
            }
            TCG_COMMIT_MC(EMPTYB(sb, s));
        }
    }

    if (tid < 256) {
        MBAR_WAIT(EMPTYB(sb, (NK2 - 1) % NSTG2), (uint32_t)(((NK2 - 1) / NSTG2) & 1));
        TCG_FENCE_AFTER();
        const int wg = wid >> 2;
        const int o = n0 + (int)rank * 128 + ((wid & 3) << 5) + lid;
        const float sc = dsc[o] * 16.0f;
#pragma unroll
        for (int cc = 0; cc < 4; cc++) {
            const int cb = wg * 128 + cc * 32;
            uint32_t dr[32];
            LDTM_X32(dr, tb + (uint32_t)cb);
            TCG_WAIT_LD();
#pragma unroll
            for (int j = 0; j < 32; j++)
                out[(size_t)(t0 + cb + j) * HID + o] = __uint_as_float(dr[j]) * sc;
        }
    }
    __syncthreads();
    CLUSTER_SYNC();
    if (wid == 0) { TCG_RELQ2(); TCG_DEALLOC2(tb, 256); }
    CLUSTER_SYNC();
#endif
}

extern "C" void kernel_launch(void* const* d_in, const int* in_sizes, int n_in,
                              void* d_out, int out_size) {
    const float* x  = (const float*)d_in[0];
    const int*  w1  = (const int*)d_in[1];
    const float* gus = (const float*)d_in[2];
    const int*  w2  = (const int*)d_in[3];
    const float* dsc = (const float*)d_in[4];
    float* out = (float*)d_out;

    void *p_xh, *p_w1, *p_w2;
    cudaGetSymbolAddress(&p_xh, g_xh);
    cudaGetSymbolAddress(&p_w1, g_w1h);
    cudaGetSymbolAddress(&p_w2, g_w2h);

    unsigned gx = (unsigned)((size_t)TOK * HID / 8);
    unsigned gw1 = (unsigned)((size_t)2 * INTERC * HID / 8);
    unsigned gw2 = (unsigned)((size_t)HID * INTERC / 8);
    cvt_f32_t<<<(gx + 255) / 256, 256>>>(x, (__half*)p_xh, HID, gx);
    cvt_i32_t<<<(gw1 + 255) / 256, 256>>>(w1, (__half*)p_w1, HID, gw1);
    cvt_i32_t<<<(gw2 + 255) / 256, 256>>>(w2, (__half*)p_w2, INTERC, gw2);

    cudaFuncSetAttribute(ffn_gemm1, cudaFuncAttributeMaxDynamicSharedMemorySize, SMEM1);
    cudaFuncSetAttribute(ffn_gemm2, cudaFuncAttributeMaxDynamicSharedMemorySize, SMEM2);

    dim3 g1(2, TOK / 256, INTERC / 256);
    ffn_gemm1<<<g1, 320, SMEM1>>>(gus);
    dim3 g2(2, TOK / 256, HID / 256);
    ffn_gemm2<<<g2, 320, SMEM2>>>(dsc, out);
}

// round 16
// speedup vs baseline: 1.0288x; 1.0288x over previous
#include <cuda_runtime.h>
#include <cuda_fp16.h>
#include <cstdint>

#define TOK    8192
#define HID    3072
#define INTERC 8192
#define KT     64
#define NK1    (HID / KT)     // 48
#define NK2    (INTERC / KT)  // 128
#define TILEB  16384u         // one 128x64 f16 tile, swizzled, bytes

// GEMM1: weight ring (Ag+Au, 32KB stages) + B ring (16KB stages)
#define NSW1   4
#define NSB1   6
#define W1_OFF 1024u
#define B1_OFF (1024u + NSW1 * 32768u)          // 132096
#define SMEM1  (B1_OFF + NSB1 * 16384u)          // 230400
// GEMM2: 6 stages of [A 16K | B 16K]
#define NSTG2  6
#define STG2   32768u
#define SMEM2  (1024u + NSTG2 * STG2)            // 197632

// cg2 kind::f16: dtype=F32, a/b=F16, N=256, M=256
#define IDESC2 ((1u << 4) | (32u << 17) | (16u << 24))

#if !defined(__CUDA_ARCH__) || defined(__CUDA_ARCH_FEAT_SM103_ALL) || defined(__CUDA_ARCH_FEAT_SM100_ALL) || defined(__CUDA_ARCH_FEAT_SM101_ALL)
#define HAS_TCGEN05 1
#else
#define HAS_TCGEN05 0
#endif

// tiled+swizzled scratch: [rowblock][kchunk][16KB tile]
__device__ __align__(1024) __half g_xh [(size_t)TOK * HID];
__device__ __align__(1024) __half g_w1h[(size_t)(2 * INTERC) * HID];
__device__ __align__(1024) __half g_w2h[(size_t)HID * INTERC];
__device__ __align__(1024) __half g_hid[(size_t)TOK * INTERC];

__device__ __forceinline__ uint32_t smem_u32(const void* p) {
    uint32_t a;
    asm("{ .reg .u64 t; cvta.to.shared.u64 t, %1; cvt.u32.u64 %0, t; }" : "=r"(a) : "l"(p));
    return a;
}
#define SWZ(o) ((o) ^ (((o) >> 3) & 0x70))

// GEMM1 barrier slots (header): wfull[4]@32, wempty[4]@64, bfull[6]@96,
// bempty[6]@144, gfull[4]@192
#define WFULL(sb, s)   ((sb) + 32u + 8u * (uint32_t)(s))
#define WEMPTY(sb, s)  ((sb) + 64u + 8u * (uint32_t)(s))
#define BFULL(sb, s)   ((sb) + 96u + 8u * (uint32_t)(s))
#define BEMPTY(sb, s)  ((sb) + 144u + 8u * (uint32_t)(s))
#define GFULL1(sb, s)  ((sb) + 192u + 8u * (uint32_t)(s))
// GEMM2 slots
#define LFULL(sb, s)   ((sb) + 32u + 32u * (uint32_t)(s))
#define EMPTYB(sb, s)  ((sb) + 40u + 32u * (uint32_t)(s))
#define GFULL(sb, s)   ((sb) + 48u + 32u * (uint32_t)(s))

__device__ __forceinline__ uint64_t make_desc(uint32_t addr) {
    const uint64_t base = (uint64_t(2) << 61) | (uint64_t(1) << 46) |
                          (uint64_t(64) << 32) | (uint64_t(1) << 16);
    return base | ((uint64_t)(addr >> 4) & 0x3FFF);
}
__device__ __forceinline__ void cpa16(uint32_t dst, const void* src) {
    asm volatile("cp.async.cg.shared.global [%0], [%1], 16;" :: "r"(dst), "l"(src));
}
__device__ __forceinline__ void cpa_arrive(uint32_t mbar) {
    asm volatile("cp.async.mbarrier.arrive.noinc.shared.b64 [%0];" :: "r"(mbar) : "memory");
}
// pre-swizzled contiguous 16KB tile: straight memcpy, 256 threads x 4 x 16B
__device__ __forceinline__ void copy_tile(uint32_t sdst, const char* src, int tid) {
#pragma unroll
    for (int i = 0; i < 4; i++) {
        uint32_t off = (uint32_t)(tid * 16 + i * 4096);
        cpa16(sdst + off, src + off);
    }
}

#if HAS_TCGEN05
__device__ __forceinline__ void mma2_f16_ss(uint32_t d, uint64_t a, uint64_t b, uint32_t en) {
    asm volatile("{\n\t.reg .pred p;\n\tsetp.ne.u32 p, %4, 0;\n\t"
        "tcgen05.mma.cta_group::2.kind::f16 [%0], %1, %2, %3, {%5, %5, %5, %5, %5, %5, %5, %5}, p;\n\t}"
        :: "r"(d), "l"(a), "l"(b), "r"(IDESC2), "r"(en), "r"(0u) : "memory");
}
#define TCG_ALLOC2(sa, n)  asm volatile("tcgen05.alloc.cta_group::2.sync.aligned.shared::cta.b32 [%0], %1;" :: "r"(sa), "r"((uint32_t)(n)) : "memory")
#define TCG_DEALLOC2(t, n) asm volatile("tcgen05.dealloc.cta_group::2.sync.aligned.b32 %0, %1;" :: "r"(t), "r"((uint32_t)(n)))
#define TCG_RELQ2()        asm volatile("tcgen05.relinquish_alloc_permit.cta_group::2.sync.aligned;")
#define TCG_COMMIT_MC(a)   asm volatile("tcgen05.commit.cta_group::2.mbarrier::arrive::one.shared::cluster.multicast::cluster.b64 [%0], %1;" :: "r"(a), "h"((uint16_t)3) : "memory")
#define TCG_FENCE_AFTER()  asm volatile("tcgen05.fence::after_thread_sync;" ::: "memory")
#define TCG_WAIT_LD()      asm volatile("tcgen05.wait::ld.sync.aligned;" ::: "memory")

#define LDTM_X32(r, a)                                                            \
    asm volatile("tcgen05.ld.sync.aligned.32x32b.x32.b32 "                        \
        "{%0, %1, %2, %3, %4, %5, %6, %7, %8, %9, %10, %11, %12, %13, %14, %15, " \
        " %16, %17, %18, %19, %20, %21, %22, %23, %24, %25, %26, %27, %28, %29, %30, %31}, [%32];" \
        : "=r"((r)[0]),  "=r"((r)[1]),  "=r"((r)[2]),  "=r"((r)[3]),              \
          "=r"((r)[4]),  "=r"((r)[5]),  "=r"((r)[6]),  "=r"((r)[7]),              \
          "=r"((r)[8]),  "=r"((r)[9]),  "=r"((r)[10]), "=r"((r)[11]),             \
          "=r"((r)[12]), "=r"((r)[13]), "=r"((r)[14]), "=r"((r)[15]),             \
          "=r"((r)[16]), "=r"((r)[17]), "=r"((r)[18]), "=r"((r)[19]),             \
          "=r"((r)[20]), "=r"((r)[21]), "=r"((r)[22]), "=r"((r)[23]),             \
          "=r"((r)[24]), "=r"((r)[25]), "=r"((r)[26]), "=r"((r)[27]),             \
          "=r"((r)[28]), "=r"((r)[29]), "=r"((r)[30]), "=r"((r)[31])              \
        : "r"(a))
#endif

#define MBAR_INIT(a, c)   asm volatile("mbarrier.init.shared.b64 [%0], %1;" :: "r"(a), "r"((uint32_t)(c)) : "memory")
#define MBAR_WAIT(addr, ph) do {                                                 \
    uint32_t _d;                                                                 \
    asm volatile("{\n\t.reg .pred p;\n\t"                                        \
        "mbarrier.try_wait.parity.acquire.cta.shared::cta.b64 p, [%1], %2;\n\t"  \
        "selp.b32 %0, 1, 0, p;\n\t}" : "=r"(_d) : "r"(addr), "r"(ph) : "memory");\
    while (!_d)                                                                  \
        asm volatile("{\n\t.reg .pred p;\n\t"                                    \
            "mbarrier.try_wait.parity.acquire.cta.shared::cta.b64 p, [%1], %2, 0x989680;\n\t" \
            "selp.b32 %0, 1, 0, p;\n\t}" : "=r"(_d) : "r"(addr), "r"(ph) : "memory"); \
} while (0)
#define MBAR_WAIT_CL(addr, ph) do {                                              \
    uint32_t _d;                                                                 \
    asm volatile("{\n\t.reg .pred p;\n\t"                                        \
        "mbarrier.try_wait.parity.acquire.cluster.shared::cta.b64 p, [%1], %2;\n\t" \
        "selp.b32 %0, 1, 0, p;\n\t}" : "=r"(_d) : "r"(addr), "r"(ph) : "memory");\
    while (!_d)                                                                  \
        asm volatile("{\n\t.reg .pred p;\n\t"                                    \
            "mbarrier.try_wait.parity.acquire.cluster.shared::cta.b64 p, [%1], %2, 0x989680;\n\t" \
            "selp.b32 %0, 1, 0, p;\n\t}" : "=r"(_d) : "r"(addr), "r"(ph) : "memory"); \
} while (0)
#define ARRIVE_LEADER(addr)                                                      \
    asm volatile("{\n\t.reg .b32 ra;\n\t"                                        \
        "mapa.shared::cluster.u32 ra, %0, 0;\n\t"                                \
        "mbarrier.arrive.shared::cluster.b64 _, [ra];\n\t}"                      \
        :: "r"(addr) : "memory")
#define CLUSTER_SYNC() do {                                                      \
    asm volatile("barrier.cluster.arrive.aligned;" ::: "memory");                \
    asm volatile("barrier.cluster.wait.aligned;" ::: "memory");                  \
} while (0)

// ---- converts: row-major -> tiled [row/128][col/64][16KB SW128-swizzled] ------
__global__ void __launch_bounds__(256) cvt_i32_t(const int* __restrict__ s,
                                                 __half* __restrict__ d,
                                                 int cols, unsigned ngrp) {
    unsigned i = blockIdx.x * 256u + threadIdx.x;
    if (i >= ngrp) return;
    unsigned e = i * 8u;
    unsigned row = e / (unsigned)cols, col = e % (unsigned)cols;
    const int4* p = (const int4*)(s + (size_t)row * cols + col);
    int4 a = p[0], b = p[1];
    __half2 h0 = __floats2half2_rn((float)a.x, (float)a.y);
    __half2 h1 = __floats2half2_rn((float)a.z, (float)a.w);
    __half2 h2 = __floats2half2_rn((float)b.x, (float)b.y);
    __half2 h3 = __floats2half2_rn((float)b.z, (float)b.w);
    uint4 v = make_uint4(*(uint32_t*)&h0, *(uint32_t*)&h1, *(uint32_t*)&h2, *(uint32_t*)&h3);
    unsigned nkc = (unsigned)cols >> 6;
    size_t tile = (size_t)(row >> 7) * nkc + (col >> 6);
    uint32_t off = (row & 127u) * 128u + (col & 63u) * 2u;
    *(uint4*)((char*)d + tile * TILEB + SWZ(off)) = v;
}
__global__ void __launch_bounds__(256) cvt_f32_t(const float* __restrict__ s,
                                                 __half* __restrict__ d,
                                                 int cols, unsigned ngrp) {
    unsigned i = blockIdx.x * 256u + threadIdx.x;
    if (i >= ngrp) return;
    unsigned e = i * 8u;
    unsigned row = e / (unsigned)cols, col = e % (unsigned)cols;
    const float4* p = (const float4*)(s + (size_t)row * cols + col);
    float4 a = p[0], b = p[1];
    __half2 h0 = __floats2half2_rn(a.x, a.y);
    __half2 h1 = __floats2half2_rn(a.z, a.w);
    __half2 h2 = __floats2half2_rn(b.x, b.y);
    __half2 h3 = __floats2half2_rn(b.z, b.w);
    uint4 v = make_uint4(*(uint32_t*)&h0, *(uint32_t*)&h1, *(uint32_t*)&h2, *(uint32_t*)&h3);
    unsigned nkc = (unsigned)cols >> 6;
    size_t tile = (size_t)(row >> 7) * nkc + (col >> 6);
    uint32_t off = (row & 127u) * 128u + (col & 63u) * 2u;
    *(uint4*)((char*)d + tile * TILEB + SWZ(off)) = v;
}

// ---------------- GEMM1 (cg2, split W-ring/B-ring, no proxy fence) -------------
__global__ void __launch_bounds__(320, 1) __cluster_dims__(2, 1, 1)
ffn_gemm1(const float* __restrict__ gus) {
#if HAS_TCGEN05
    extern __shared__ char smem[];
    uint32_t sb = smem_u32(smem);
    const int tid = threadIdx.x, wid = tid >> 5, lid = tid & 31;
    uint32_t rank;
    asm("mov.u32 %0, %%cluster_ctarank;" : "=r"(rank));
    const int by = blockIdx.y, bz = blockIdx.z;
    const int t0 = by * 256, g0 = bz * 256;

    if (wid == 0) TCG_ALLOC2(sb, 512);
    if (tid == 0) {
#pragma unroll
        for (int s = 0; s < NSW1; s++) {
            MBAR_INIT(WFULL(sb, s), 256);
            MBAR_INIT(WEMPTY(sb, s), 1);
            MBAR_INIT(GFULL1(sb, s), 2);
        }
#pragma unroll
        for (int s = 0; s < NSB1; s++) {
            MBAR_INIT(BFULL(sb, s), 256);
            MBAR_INIT(BEMPTY(sb, s), 1);
        }
    }
    __syncthreads();
    uint32_t tb;
    asm volatile("ld.shared.b32 %0, [%1];" : "=r"(tb) : "r"(sb));
    CLUSTER_SYNC();

    const char* wb = (const char*)g_w1h;
    const char* xb = (const char*)g_xh;
    const size_t rbg = (size_t)(2 * bz + (int)rank);
    const size_t rbu = (size_t)(INTERC / 128 + 2 * bz + (int)rank);
    const size_t rbx = (size_t)(2 * by + (int)rank);

    if (tid < 256) {
        for (int kc = 0; kc < NK1; kc++) {
            const int sw = kc % NSW1, sbi = kc % NSB1;
            if (kc >= NSW1)
                MBAR_WAIT(WEMPTY(sb, sw), (uint32_t)((kc / NSW1 + 1) & 1));
            const uint32_t wbase = sb + W1_OFF + (uint32_t)sw * 32768u;
            copy_tile(wbase,         wb + (rbg * NK1 + kc) * TILEB, tid);
            copy_tile(wbase + TILEB, wb + (rbu * NK1 + kc) * TILEB, tid);
            cpa_arrive(WFULL(sb, sw));
            if (kc >= NSB1)
                MBAR_WAIT(BEMPTY(sb, sbi), (uint32_t)((kc / NSB1 + 1) & 1));
            const uint32_t bbase = sb + B1_OFF + (uint32_t)sbi * 16384u;
            copy_tile(bbase, xb + (rbx * NK1 + kc) * TILEB, tid);
            cpa_arrive(BFULL(sb, sbi));
        }
    } else if (tid == 288) {
        for (int kc = 0; kc < NK1; kc++) {
            const int sw = kc % NSW1, sbi = kc % NSB1;
            MBAR_WAIT(WFULL(sb, sw), (uint32_t)((kc / NSW1) & 1));
            MBAR_WAIT(BFULL(sb, sbi), (uint32_t)((kc / NSB1) & 1));
            ARRIVE_LEADER(GFULL1(sb, sw));
        }
    } else if (tid == 256 && rank == 0) {
        for (int kc = 0; kc < NK1; kc++) {
            const int sw = kc % NSW1, sbi = kc % NSB1;
            MBAR_WAIT_CL(GFULL1(sb, sw), (uint32_t)((kc / NSW1) & 1));
            const uint32_t wbase = sb + W1_OFF + (uint32_t)sw * 32768u;
            const uint32_t bbase = sb + B1_OFF + (uint32_t)sbi * 16384u;
            uint64_t ad = make_desc(wbase);
            uint64_t au = make_desc(wbase + TILEB);
            uint64_t bd = make_desc(bbase);
#pragma unroll
            for (int ks = 0; ks < 4; ks++) {
                uint32_t en = (kc | ks) ? 1u : 0u;
                mma2_f16_ss(tb,        ad + ks * 2, bd + ks * 2, en);
                mma2_f16_ss(tb + 256u, au + ks * 2, bd + ks * 2, en);
            }
            TCG_COMMIT_MC(WEMPTY(sb, sw));
            TCG_COMMIT_MC(BEMPTY(sb, sbi));
        }
    }

    if (tid < 256) {
        MBAR_WAIT(WEMPTY(sb, (NK1 - 1) % NSW1), (uint32_t)(((NK1 - 1) / NSW1) & 1));
        TCG_FENCE_AFTER();
        const int wg = wid >> 2;
        const int o = g0 + (int)rank * 128 + ((wid & 3) << 5) + lid;
        const float sg = gus[o], su = gus[INTERC + o];
        char* hb = (char*)g_hid;
        const size_t tilebase = ((size_t)(2 * by + wg) * NK2 + (size_t)(o >> 6)) * TILEB;
        const uint32_t oc = (uint32_t)(o & 63) * 2u;
#pragma unroll
        for (int cc = 0; cc < 4; cc++) {
            const int cb = wg * 128 + cc * 32;
            uint32_t gr[32], ur[32];
            LDTM_X32(gr, tb + (uint32_t)cb);
            LDTM_X32(ur, tb + 256u + (uint32_t)cb);
            TCG_WAIT_LD();
#pragma unroll
            for (int j = 0; j < 32; j++) {
                float g = __uint_as_float(gr[j]) * sg;
                float u = __uint_as_float(ur[j]) * su;
                float h = g * u * 0.0625f / (1.0f + __expf(-g));
                uint32_t off = (uint32_t)(cc * 32 + j) * 128u + oc;
                *(__half*)(hb + tilebase + SWZ(off)) = __float2half_rn(h);
            }
        }
    }
    __syncthreads();
    CLUSTER_SYNC();
    if (wid == 0) { TCG_RELQ2(); TCG_DEALLOC2(tb, 512); }
    CLUSTER_SYNC();
#endif
}

// ---------------- GEMM2 (cg2, no proxy fence) ----------------------------------
__global__ void __launch_bounds__(320, 1) __cluster_dims__(2, 1, 1)
ffn_gemm2(const float* __restrict__ dsc, float* __restrict__ out) {
#if HAS_TCGEN05
    extern __shared__ char smem[];
    uint32_t sb = smem_u32(smem);
    const int tid = threadIdx.x, wid = tid >> 5, lid = tid & 31;
    uint32_t rank;
    asm("mov.u32 %0, %%cluster_ctarank;" : "=r"(rank));
    const int by = blockIdx.y, bz = blockIdx.z;
    const int t0 = by * 256, n0 = bz * 256;

    if (wid == 0) TCG_ALLOC2(sb, 256);
    if (tid == 0) {
#pragma unroll
        for (int s = 0; s < NSTG2; s++) {
            MBAR_INIT(LFULL(sb, s), 256);
            MBAR_INIT(EMPTYB(sb, s), 1);
            MBAR_INIT(GFULL(sb, s), 2);
        }
    }
    __syncthreads();
    uint32_t tb;
    asm volatile("ld.shared.b32 %0, [%1];" : "=r"(tb) : "r"(sb));
    CLUSTER_SYNC();

    const char* wb = (const char*)g_w2h;
    const char* hbs = (const char*)g_hid;
    const size_t rba = (size_t)(2 * bz + (int)rank);
    const size_t rbb = (size_t)(2 * by + (int)rank);

    if (tid < 256) {
        for (int kc = 0; kc < NK2; kc++) {
            const int s = kc % NSTG2, r = kc / NSTG2;
            if (kc >= NSTG2) MBAR_WAIT(EMPTYB(sb, s), (uint32_t)((r + 1) & 1));
            const uint32_t base = sb + 1024u + (uint32_t)s * STG2;
            copy_tile(base,         wb  + (rba * NK2 + kc) * TILEB, tid);
            copy_tile(base + TILEB, hbs + (rbb * NK2 + kc) * TILEB, tid);
            cpa_arrive(LFULL(sb, s));
        }
    } else if (tid == 288) {
        for (int kc = 0; kc < NK2; kc++) {
            const int s = kc % NSTG2, r = kc / NSTG2;
            MBAR_WAIT(LFULL(sb, s), (uint32_t)(r & 1));
            ARRIVE_LEADER(GFULL(sb, s));
        }
    } else if (tid == 256 && rank == 0) {
        for (int kc = 0; kc < NK2; kc++) {
            const int s = kc % NSTG2, r = kc / NSTG2;
            MBAR_WAIT_CL(GFULL(sb, s), (uint32_t)(r & 1));
            const uint32_t base = sb + 1024u + (uint32_t)s * STG2;
            uint64_t ad = make_desc(base);
            uint64_t bd = make_desc(base + TILEB);
#pragma unroll
            for (int ks = 0; ks < 4; ks++)
                mma2_f16_ss(tb, ad + ks * 2, bd + ks * 2, (kc | ks) ? 1u : 0u);
            TCG_COMMIT_MC(EMPTYB(sb, s));
        }
    }

    if (tid < 256) {
        MBAR_WAIT(EMPTYB(sb, (NK2 - 1) % NSTG2), (uint32_t)(((NK2 - 1) / NSTG2) & 1));
        TCG_FENCE_AFTER();
        const int wg = wid >> 2;
        const int o = n0 + (int)rank * 128 + ((wid & 3) << 5) + lid;
        const float sc = dsc[o] * 16.0f;
#pragma unroll
        for (int cc = 0; cc < 4; cc++) {
            const int cb = wg * 128 + cc * 32;
            uint32_t dr[32];
            LDTM_X32(dr, tb + (uint32_t)cb);
            TCG_WAIT_LD();
#pragma unroll
            for (int j = 0; j < 32; j++)
                out[(size_t)(t0 + cb + j) * HID + o] = __uint_as_float(dr[j]) * sc;
        }
    }
    __syncthreads();
    CLUSTER_SYNC();
    if (wid == 0) { TCG_RELQ2(); TCG_DEALLOC2(tb, 256); }
    CLUSTER_SYNC();
#endif
}

extern "C" void kernel_launch(void* const* d_in, const int* in_sizes, int n_in,
                              void* d_out, int out_size) {
    const float* x  = (const float*)d_in[0];
    const int*  w1  = (const int*)d_in[1];
    const float* gus = (const float*)d_in[2];
    const int*  w2  = (const int*)d_in[3];
    const float* dsc = (const float*)d_in[4];
    float* out = (float*)d_out;

    void *p_xh, *p_w1, *p_w2;
    cudaGetSymbolAddress(&p_xh, g_xh);
    cudaGetSymbolAddress(&p_w1, g_w1h);
    cudaGetSymbolAddress(&p_w2, g_w2h);

    unsigned gx = (unsigned)((size_t)TOK * HID / 8);
    unsigned gw1 = (unsigned)((size_t)2 * INTERC * HID / 8);
    unsigned gw2 = (unsigned)((size_t)HID * INTERC / 8);
    cvt_f32_t<<<(gx + 255) / 256, 256>>>(x, (__half*)p_xh, HID, gx);
    cvt_i32_t<<<(gw1 + 255) / 256, 256>>>(w1, (__half*)p_w1, HID, gw1);
    cvt_i32_t<<<(gw2 + 255) / 256, 256>>>(w2, (__half*)p_w2, INTERC, gw2);

    cudaFuncSetAttribute(ffn_gemm1, cudaFuncAttributeMaxDynamicSharedMemorySize, SMEM1);
    cudaFuncSetAttribute(ffn_gemm2, cudaFuncAttributeMaxDynamicSharedMemorySize, SMEM2);

    dim3 g1(2, TOK / 256, INTERC / 256);
    ffn_gemm1<<<g1, 320, SMEM1>>>(gus);
    dim3 g2(2, TOK / 256, HID / 256);
    ffn_gemm2<<<g2, 320, SMEM2>>>(dsc, out);
}

// round 17
// speedup vs baseline: 1.0483x; 1.0189x over previous
#include <cuda_runtime.h>
#include <cuda_fp16.h>
#include <cstdint>

#define TOK    8192
#define HID    3072
#define INTERC 8192
#define KT     64
#define NK1    (HID / KT)     // 48
#define NK2    (INTERC / KT)  // 128
#define TILEB  16384u         // one 128x64 f16 tile, swizzled, bytes

// GEMM1: 2 stages of [Wg 16K | Wu 16K | B 8K] = 40KB  (occ 2)
#define NSTG1  2
#define STG1   40960u
#define SMEM1  (1024u + NSTG1 * STG1)   // 82944
// GEMM2: 3 stages of [A 16K | B 16K] = 32KB            (occ 2)
#define NSTG2  3
#define STG2   32768u
#define SMEM2  (1024u + NSTG2 * STG2)   // 99328

// cg2 kind::f16: dtype=F32, M=256; N=128 (GEMM1) / N=256 (GEMM2)
#define IDESC_N128 ((1u << 4) | (16u << 17) | (16u << 24))
#define IDESC_N256 ((1u << 4) | (32u << 17) | (16u << 24))

#if !defined(__CUDA_ARCH__) || defined(__CUDA_ARCH_FEAT_SM103_ALL) || defined(__CUDA_ARCH_FEAT_SM100_ALL) || defined(__CUDA_ARCH_FEAT_SM101_ALL)
#define HAS_TCGEN05 1
#else
#define HAS_TCGEN05 0
#endif

__device__ __align__(1024) __half g_xh [(size_t)TOK * HID];
__device__ __align__(1024) __half g_w1h[(size_t)(2 * INTERC) * HID];
__device__ __align__(1024) __half g_w2h[(size_t)HID * INTERC];
__device__ __align__(1024) __half g_hid[(size_t)TOK * INTERC];

__device__ __forceinline__ uint32_t smem_u32(const void* p) {
    uint32_t a;
    asm("{ .reg .u64 t; cvta.to.shared.u64 t, %1; cvt.u32.u64 %0, t; }" : "=r"(a) : "l"(p));
    return a;
}
#define SWZ(o) ((o) ^ (((o) >> 3) & 0x70))

#define LFULL(sb, s)  ((sb) + 32u + 32u * (uint32_t)(s))
#define EMPTYB(sb, s) ((sb) + 40u + 32u * (uint32_t)(s))
#define GFULL(sb, s)  ((sb) + 48u + 32u * (uint32_t)(s))

__device__ __forceinline__ uint64_t make_desc(uint32_t addr) {
    const uint64_t base = (uint64_t(2) << 61) | (uint64_t(1) << 46) |
                          (uint64_t(64) << 32) | (uint64_t(1) << 16);
    return base | ((uint64_t)(addr >> 4) & 0x3FFF);
}
__device__ __forceinline__ void cpa16(uint32_t dst, const void* src) {
    asm volatile("cp.async.cg.shared.global [%0], [%1], 16;" :: "r"(dst), "l"(src));
}
__device__ __forceinline__ void cpa_arrive(uint32_t mbar) {
    asm volatile("cp.async.mbarrier.arrive.noinc.shared.b64 [%0];" :: "r"(mbar) : "memory");
}
// pre-swizzled contiguous 16KB tile: 256 threads x 4 x 16B
__device__ __forceinline__ void copy_tile(uint32_t sdst, const char* src, int tid) {
#pragma unroll
    for (int i = 0; i < 4; i++) {
        uint32_t off = (uint32_t)(tid * 16 + i * 4096);
        cpa16(sdst + off, src + off);
    }
}
// contiguous 8KB half-tile: 256 threads x 2 x 16B
__device__ __forceinline__ void copy_half(uint32_t sdst, const char* src, int tid) {
#pragma unroll
    for (int i = 0; i < 2; i++) {
        uint32_t off = (uint32_t)(tid * 16 + i * 4096);
        cpa16(sdst + off, src + off);
    }
}

#if HAS_TCGEN05
__device__ __forceinline__ void mma2_f16_ss(uint32_t d, uint64_t a, uint64_t b,
                                            uint32_t idesc, uint32_t en) {
    asm volatile("{\n\t.reg .pred p;\n\tsetp.ne.u32 p, %4, 0;\n\t"
        "tcgen05.mma.cta_group::2.kind::f16 [%0], %1, %2, %3, {%5, %5, %5, %5, %5, %5, %5, %5}, p;\n\t}"
        :: "r"(d), "l"(a), "l"(b), "r"(idesc), "r"(en), "r"(0u) : "memory");
}
#define TCG_ALLOC2(sa, n)  asm volatile("tcgen05.alloc.cta_group::2.sync.aligned.shared::cta.b32 [%0], %1;" :: "r"(sa), "r"((uint32_t)(n)) : "memory")
#define TCG_DEALLOC2(t, n) asm volatile("tcgen05.dealloc.cta_group::2.sync.aligned.b32 %0, %1;" :: "r"(t), "r"((uint32_t)(n)))
#define TCG_RELQ2()        asm volatile("tcgen05.relinquish_alloc_permit.cta_group::2.sync.aligned;")
#define TCG_COMMIT_MC(a)   asm volatile("tcgen05.commit.cta_group::2.mbarrier::arrive::one.shared::cluster.multicast::cluster.b64 [%0], %1;" :: "r"(a), "h"((uint16_t)3) : "memory")
#define TCG_FENCE_AFTER()  asm volatile("tcgen05.fence::after_thread_sync;" ::: "memory")
#define TCG_WAIT_LD()      asm volatile("tcgen05.wait::ld.sync.aligned;" ::: "memory")

#define LDTM_X32(r, a)                                                            \
    asm volatile("tcgen05.ld.sync.aligned.32x32b.x32.b32 "                        \
        "{%0, %1, %2, %3, %4, %5, %6, %7, %8, %9, %10, %11, %12, %13, %14, %15, " \
        " %16, %17, %18, %19, %20, %21, %22, %23, %24, %25, %26, %27, %28, %29, %30, %31}, [%32];" \
        : "=r"((r)[0]),  "=r"((r)[1]),  "=r"((r)[2]),  "=r"((r)[3]),              \
          "=r"((r)[4]),  "=r"((r)[5]),  "=r"((r)[6]),  "=r"((r)[7]),              \
          "=r"((r)[8]),  "=r"((r)[9]),  "=r"((r)[10]), "=r"((r)[11]),             \
          "=r"((r)[12]), "=r"((r)[13]), "=r"((r)[14]), "=r"((r)[15]),             \
          "=r"((r)[16]), "=r"((r)[17]), "=r"((r)[18]), "=r"((r)[19]),             \
          "=r"((r)[20]), "=r"((r)[21]), "=r"((r)[22]), "=r"((r)[23]),             \
          "=r"((r)[24]), "=r"((r)[25]), "=r"((r)[26]), "=r"((r)[27]),             \
          "=r"((r)[28]), "=r"((r)[29]), "=r"((r)[30]), "=r"((r)[31])              \
        : "r"(a))
#endif

#define MBAR_INIT(a, c)   asm volatile("mbarrier.init.shared.b64 [%0], %1;" :: "r"(a), "r"((uint32_t)(c)) : "memory")
#define MBAR_WAIT(addr, ph) do {                                                 \
    uint32_t _d;                                                                 \
    asm volatile("{\n\t.reg .pred p;\n\t"                                        \
        "mbarrier.try_wait.parity.acquire.cta.shared::cta.b64 p, [%1], %2;\n\t"  \
        "selp.b32 %0, 1, 0, p;\n\t}" : "=r"(_d) : "r"(addr), "r"(ph) : "memory");\
    while (!_d)                                                                  \
        asm volatile("{\n\t.reg .pred p;\n\t"                                    \
            "mbarrier.try_wait.parity.acquire.cta.shared::cta.b64 p, [%1], %2, 0x989680;\n\t" \
            "selp.b32 %0, 1, 0, p;\n\t}" : "=r"(_d) : "r"(addr), "r"(ph) : "memory"); \
} while (0)
#define MBAR_WAIT_CL(addr, ph) do {                                              \
    uint32_t _d;                                                                 \
    asm volatile("{\n\t.reg .pred p;\n\t"                                        \
        "mbarrier.try_wait.parity.acquire.cluster.shared::cta.b64 p, [%1], %2;\n\t" \
        "selp.b32 %0, 1, 0, p;\n\t}" : "=r"(_d) : "r"(addr), "r"(ph) : "memory");\
    while (!_d)                                                                  \
        asm volatile("{\n\t.reg .pred p;\n\t"                                    \
            "mbarrier.try_wait.parity.acquire.cluster.shared::cta.b64 p, [%1], %2, 0x989680;\n\t" \
            "selp.b32 %0, 1, 0, p;\n\t}" : "=r"(_d) : "r"(addr), "r"(ph) : "memory"); \
} while (0)
#define ARRIVE_LEADER(addr)                                                      \
    asm volatile("{\n\t.reg .b32 ra;\n\t"                                        \
        "mapa.shared::cluster.u32 ra, %0, 0;\n\t"                                \
        "mbarrier.arrive.shared::cluster.b64 _, [ra];\n\t}"                      \
        :: "r"(addr) : "memory")
#define CLUSTER_SYNC() do {                                                      \
    asm volatile("barrier.cluster.arrive.aligned;" ::: "memory");                \
    asm volatile("barrier.cluster.wait.aligned;" ::: "memory");                  \
} while (0)

// ---- converts: row-major -> tiled [row/128][col/64][16KB SW128-swizzled] ------
__global__ void __launch_bounds__(256) cvt_i32_t(const int* __restrict__ s,
                                                 __half* __restrict__ d,
                                                 int cols, unsigned ngrp) {
    unsigned i = blockIdx.x * 256u + threadIdx.x;
    if (i >= ngrp) return;
    unsigned e = i * 8u;
    unsigned row = e / (unsigned)cols, col = e % (unsigned)cols;
    const int4* p = (const int4*)(s + (size_t)row * cols + col);
    int4 a = p[0], b = p[1];
    __half2 h0 = __floats2half2_rn((float)a.x, (float)a.y);
    __half2 h1 = __floats2half2_rn((float)a.z, (float)a.w);
    __half2 h2 = __floats2half2_rn((float)b.x, (float)b.y);
    __half2 h3 = __floats2half2_rn((float)b.z, (float)b.w);
    uint4 v = make_uint4(*(uint32_t*)&h0, *(uint32_t*)&h1, *(uint32_t*)&h2, *(uint32_t*)&h3);
    unsigned nkc = (unsigned)cols >> 6;
    size_t tile = (size_t)(row >> 7) * nkc + (col >> 6);
    uint32_t off = (row & 127u) * 128u + (col & 63u) * 2u;
    *(uint4*)((char*)d + tile * TILEB + SWZ(off)) = v;
}
__global__ void __launch_bounds__(256) cvt_f32_t(const float* __restrict__ s,
                                                 __half* __restrict__ d,
                                                 int cols, unsigned ngrp) {
    unsigned i = blockIdx.x * 256u + threadIdx.x;
    if (i >= ngrp) return;
    unsigned e = i * 8u;
    unsigned row = e / (unsigned)cols, col = e % (unsigned)cols;
    const float4* p = (const float4*)(s + (size_t)row * cols + col);
    float4 a = p[0], b = p[1];
    __half2 h0 = __floats2half2_rn(a.x, a.y);
    __half2 h1 = __floats2half2_rn(a.z, a.w);
    __half2 h2 = __floats2half2_rn(b.x, b.y);
    __half2 h3 = __floats2half2_rn(b.z, b.w);
    uint4 v = make_uint4(*(uint32_t*)&h0, *(uint32_t*)&h1, *(uint32_t*)&h2, *(uint32_t*)&h3);
    unsigned nkc = (unsigned)cols >> 6;
    size_t tile = (size_t)(row >> 7) * nkc + (col >> 6);
    uint32_t off = (row & 127u) * 128u + (col & 63u) * 2u;
    *(uint4*)((char*)d + tile * TILEB + SWZ(off)) = v;
}

// ---------------- GEMM1 (cg2, 256x128 tile, occ 2) -----------------------------
__global__ void __launch_bounds__(320, 2) __cluster_dims__(2, 1, 1)
ffn_gemm1(const float* __restrict__ gus) {
#if HAS_TCGEN05
    extern __shared__ char smem[];
    uint32_t sb = smem_u32(smem);
    const int tid = threadIdx.x, wid = tid >> 5, lid = tid & 31;
    uint32_t rank;
    asm("mov.u32 %0, %%cluster_ctarank;" : "=r"(rank));
    const int by = blockIdx.y, bz = blockIdx.z;
    const int t0 = by * 128, g0 = bz * 256;

    if (wid == 0) { TCG_ALLOC2(sb, 256); TCG_RELQ2(); }
    if (tid == 0) {
#pragma unroll
        for (int s = 0; s < NSTG1; s++) {
            MBAR_INIT(LFULL(sb, s), 256);
            MBAR_INIT(EMPTYB(sb, s), 1);
            MBAR_INIT(GFULL(sb, s), 2);
        }
    }
    __syncthreads();
    uint32_t tb;
    asm volatile("ld.shared.b32 %0, [%1];" : "=r"(tb) : "r"(sb));
    CLUSTER_SYNC();

    const char* wb = (const char*)g_w1h;
    const char* xb = (const char*)g_xh;
    const size_t rbg = (size_t)(2 * bz + (int)rank);                 // gate rowblock
    const size_t rbu = (size_t)(INTERC / 128 + 2 * bz + (int)rank);  // up rowblock
    const size_t rbx = (size_t)by;                                   // token rowblock (128 tok)

    if (tid < 256) {
        for (int kc = 0; kc < NK1; kc++) {
            const int s = kc % NSTG1;
            if (kc >= NSTG1)
                MBAR_WAIT(EMPTYB(sb, s), (uint32_t)((kc / NSTG1 + 1) & 1));
            const uint32_t base = sb + 1024u + (uint32_t)s * STG1;
            copy_tile(base,          wb + (rbg * NK1 + kc) * TILEB, tid);
            copy_tile(base + 16384u, wb + (rbu * NK1 + kc) * TILEB, tid);
            copy_half(base + 32768u, xb + (rbx * NK1 + kc) * TILEB + rank * 8192u, tid);
            cpa_arrive(LFULL(sb, s));
        }
    } else if (tid == 288) {
        for (int kc = 0; kc < NK1; kc++) {
            const int s = kc % NSTG1, r = kc / NSTG1;
            MBAR_WAIT(LFULL(sb, s), (uint32_t)(r & 1));
            ARRIVE_LEADER(GFULL(sb, s));
        }
    } else if (tid == 256 && rank == 0) {
        for (int kc = 0; kc < NK1; kc++) {
            const int s = kc % NSTG1, r = kc / NSTG1;
            MBAR_WAIT_CL(GFULL(sb, s), (uint32_t)(r & 1));
            const uint32_t base = sb + 1024u + (uint32_t)s * STG1;
            uint64_t ad = make_desc(base);
            uint64_t au = make_desc(base + 16384u);
            uint64_t bd = make_desc(base + 32768u);
#pragma unroll
            for (int ks = 0; ks < 4; ks++) {
                uint32_t en = (kc | ks) ? 1u : 0u;
                mma2_f16_ss(tb,        ad + ks * 2, bd + ks * 2, IDESC_N128, en);
                mma2_f16_ss(tb + 128u, au + ks * 2, bd + ks * 2, IDESC_N128, en);
            }
            TCG_COMMIT_MC(EMPTYB(sb, s));
        }
    }

    if (tid < 256) {
        MBAR_WAIT(EMPTYB(sb, (NK1 - 1) % NSTG1), (uint32_t)(((NK1 - 1) / NSTG1) & 1));
        TCG_FENCE_AFTER();
        const int wg = wid >> 2;                    // token-col half (0/1)
        const int sp = wid & 3;                     // subpartition
        const int o = g0 + (int)rank * 128 + sp * 32 + lid;
        const float sg = gus[o], su = gus[INTERC + o];
        char* hb = (char*)g_hid;
        const size_t tilebase = ((size_t)by * NK2 + (size_t)(o >> 6)) * TILEB;
        const uint32_t oc = (uint32_t)(o & 63) * 2u;
#pragma unroll
        for (int cc = 0; cc < 2; cc++) {
            const int cb = wg * 64 + cc * 32;       // token col block
            uint32_t gr[32], ur[32];
            LDTM_X32(gr, tb + (uint32_t)cb);
            LDTM_X32(ur, tb + 128u + (uint32_t)cb);
            TCG_WAIT_LD();
#pragma unroll
            for (int j = 0; j < 32; j++) {
                float g = __uint_as_float(gr[j]) * sg;
                float u = __uint_as_float(ur[j]) * su;
                float h = g * u * 0.0625f / (1.0f + __expf(-g));
                uint32_t off = (uint32_t)(cb + j) * 128u + oc;
                *(__half*)(hb + tilebase + SWZ(off)) = __float2half_rn(h);
            }
        }
    }
    __syncthreads();
    CLUSTER_SYNC();
    if (wid == 0) TCG_DEALLOC2(tb, 256);
    CLUSTER_SYNC();
#endif
}

// ---------------- GEMM2 (cg2, 256x256 tile, 3 stages, occ 2) -------------------
__global__ void __launch_bounds__(320, 2) __cluster_dims__(2, 1, 1)
ffn_gemm2(const float* __restrict__ dsc, float* __restrict__ out) {
#if HAS_TCGEN05
    extern __shared__ char smem[];
    uint32_t sb = smem_u32(smem);
    const int tid = threadIdx.x, wid = tid >> 5, lid = tid & 31;
    uint32_t rank;
    asm("mov.u32 %0, %%cluster_ctarank;" : "=r"(rank));
    const int by = blockIdx.y, bz = blockIdx.z;
    const int t0 = by * 256, n0 = bz * 256;

    if (wid == 0) { TCG_ALLOC2(sb, 256); TCG_RELQ2(); }
    if (tid == 0) {
#pragma unroll
        for (int s = 0; s < NSTG2; s++) {
            MBAR_INIT(LFULL(sb, s), 256);
            MBAR_INIT(EMPTYB(sb, s), 1);
            MBAR_INIT(GFULL(sb, s), 2);
        }
    }
    __syncthreads();
    uint32_t tb;
    asm volatile("ld.shared.b32 %0, [%1];" : "=r"(tb) : "r"(sb));
    CLUSTER_SYNC();

    const char* wb = (const char*)g_w2h;
    const char* hbs = (const char*)g_hid;
    const size_t rba = (size_t)(2 * bz + (int)rank);
    const size_t rbb = (size_t)(2 * by + (int)rank);

    if (tid < 256) {
        for (int kc = 0; kc < NK2; kc++) {
            const int s = kc % NSTG2, r = kc / NSTG2;
            if (kc >= NSTG2) MBAR_WAIT(EMPTYB(sb, s), (uint32_t)((r + 1) & 1));
            const uint32_t base = sb + 1024u + (uint32_t)s * STG2;
            copy_tile(base,         wb  + (rba * NK2 + kc) * TILEB, tid);
            copy_tile(base + TILEB, hbs + (rbb * NK2 + kc) * TILEB, tid);
            cpa_arrive(LFULL(sb, s));
        }
    } else if (tid == 288) {
        for (int kc = 0; kc < NK2; kc++) {
            const int s = kc % NSTG2, r = kc / NSTG2;
            MBAR_WAIT(LFULL(sb, s), (uint32_t)(r & 1));
            ARRIVE_LEADER(GFULL(sb, s));
        }
    } else if (tid == 256 && rank == 0) {
        for (int kc = 0; kc < NK2; kc++) {
            const int s = kc % NSTG2, r = kc / NSTG2;
            MBAR_WAIT_CL(GFULL(sb, s), (uint32_t)(r & 1));
            const uint32_t base = sb + 1024u + (uint32_t)s * STG2;
            uint64_t ad = make_desc(base);
            uint64_t bd = make_desc(base + TILEB);
#pragma unroll
            for (int ks = 0; ks < 4; ks++)
                mma2_f16_ss(tb, ad + ks * 2, bd + ks * 2, IDESC_N256,
                            (kc | ks) ? 1u : 0u);
            TCG_COMMIT_MC(EMPTYB(sb, s));
        }
    }

    if (tid < 256) {
        MBAR_WAIT(EMPTYB(sb, (NK2 - 1) % NSTG2), (uint32_t)(((NK2 - 1) / NSTG2) & 1));
        TCG_FENCE_AFTER();
        const int wg = wid >> 2;
        const int o = n0 + (int)rank * 128 + ((wid & 3) << 5) + lid;
        const float sc = dsc[o] * 16.0f;
#pragma unroll
        for (int cc = 0; cc < 4; cc++) {
            const int cb = wg * 128 + cc * 32;
            uint32_t dr[32];
            LDTM_X32(dr, tb + (uint32_t)cb);
            TCG_WAIT_LD();
#pragma unroll
            for (int j = 0; j < 32; j++)
                out[(size_t)(t0 + cb + j) * HID + o] = __uint_as_float(dr[j]) * sc;
        }
    }
    __syncthreads();
    CLUSTER_SYNC();
    if (wid == 0) TCG_DEALLOC2(tb, 256);
    CLUSTER_SYNC();
#endif
}

extern "C" void kernel_launch(void* const* d_in, const int* in_sizes, int n_in,
                              void* d_out, int out_size) {
    const float* x  = (const float*)d_in[0];
    const int*  w1  = (const int*)d_in[1];
    const float* gus = (const float*)d_in[2];
    const int*  w2  = (const int*)d_in[3];
    const float* dsc = (const float*)d_in[4];
    float* out = (float*)d_out;

    void *p_xh, *p_w1, *p_w2;
    cudaGetSymbolAddress(&p_xh, g_xh);
    cudaGetSymbolAddress(&p_w1, g_w1h);
    cudaGetSymbolAddress(&p_w2, g_w2h);

    unsigned gx = (unsigned)((size_t)TOK * HID / 8);
    unsigned gw1 = (unsigned)((size_t)2 * INTERC * HID / 8);
    unsigned gw2 = (unsigned)((size_t)HID * INTERC / 8);
    cvt_f32_t<<<(gx + 255) / 256, 256>>>(x, (__half*)p_xh, HID, gx);
    cvt_i32_t<<<(gw1 + 255) / 256, 256>>>(w1, (__half*)p_w1, HID, gw1);
    cvt_i32_t<<<(gw2 + 255) / 256, 256>>>(w2, (__half*)p_w2, INTERC, gw2);

    cudaFuncSetAttribute(ffn_gemm1, cudaFuncAttributeMaxDynamicSharedMemorySize, SMEM1);
    cudaFuncSetAttribute(ffn_gemm2, cudaFuncAttributeMaxDynamicSharedMemorySize, SMEM2);

    dim3 g1(2, TOK / 128, INTERC / 256);
    ffn_gemm1<<<g1, 320, SMEM1>>>(gus);
    dim3 g2(2, TOK / 256, HID / 256);
    ffn_gemm2<<<g2, 320, SMEM2>>>(dsc, out);
}